// round 2
// baseline (speedup 1.0000x reference)
#include <cuda_runtime.h>
#include <math.h>

// ---------------- problem constants ----------------
constexpr int Bsz    = 2048;
constexpr int NSTEPS = 25;
constexpr int D0 = 100;   // noise input
constexpr int D1 = 128, D2 = 256, D3 = 512, D4 = 1024, D5 = 784;

#define BM 64
#define BN 64
#define BK 16
#define PAD 4

// ---------------- persistent device state ----------------
__device__ float g_cur1[Bsz * D1];   // relu(x@W1^T+b1), constant across steps
__device__ float g_mem1[Bsz * D1];
__device__ float g_mem2[Bsz * D2];
__device__ float g_mem3[Bsz * D3];
__device__ float g_mem4[Bsz * D4];
__device__ float g_mem5[Bsz * D5];
__device__ float g_spk1[Bsz * D1];
__device__ float g_spk2[Bsz * D2];
__device__ float g_spk3[Bsz * D3];
__device__ float g_spk4[Bsz * D4];

__device__ __forceinline__ float* sel_mem(int L) {
    switch (L) {
        case 1: return g_mem1;
        case 2: return g_mem2;
        case 3: return g_mem3;
        case 4: return g_mem4;
        default: return g_mem5;
    }
}
__device__ __forceinline__ float* sel_spk(int L) {
    switch (L) {
        case 1: return g_spk1;
        case 2: return g_spk2;
        case 3: return g_spk3;
        default: return g_spk4;
    }
}

// ---------------- zero the membrane state (every launch; graph replays) ----
__global__ void zero_mems() {
    long i = (long)blockIdx.x * blockDim.x + threadIdx.x;
    long stride = (long)gridDim.x * blockDim.x;
    for (long j = i; j < (long)Bsz * D1; j += stride) g_mem1[j] = 0.f;
    for (long j = i; j < (long)Bsz * D2; j += stride) g_mem2[j] = 0.f;
    for (long j = i; j < (long)Bsz * D3; j += stride) g_mem3[j] = 0.f;
    for (long j = i; j < (long)Bsz * D4; j += stride) g_mem4[j] = 0.f;
    for (long j = i; j < (long)Bsz * D5; j += stride) g_mem5[j] = 0.f;
}

// ---------------- LIF update for layer 1 (cur1 is precomputed) -------------
__global__ void lif1_step() {
    int i = blockIdx.x * blockDim.x + threadIdx.x;
    if (i < Bsz * D1) {
        float cur = g_cur1[i];
        float mm  = g_mem1[i];
        float rst = (mm > 1.f) ? 1.f : 0.f;
        float mn  = 0.95f * mm + cur - rst;
        g_mem1[i] = mn;
        g_spk1[i] = (mn > 1.f) ? 1.f : 0.f;
    }
}

// ---------------- fused GEMM (+bias+relu) + LIF epilogue -------------------
// cur[m,n] = relu( sum_k h[m,k]*W[n,k] + b[n] )
// MODE 0: write cur to g_cur1 (layer-1 precompute)
// MODE 1: LIF epilogue, write spike to sel_spk(layer)
// MODE 2: LIF epilogue (layer 5), write spike to spk_rec, tanh(mem) to mem_rec
template <int MODE>
__global__ void __launch_bounds__(256)
gemm_lif(const float* __restrict__ hIn, const float* __restrict__ W,
         const float* __restrict__ bias, int layer,
         float* __restrict__ spk_rec, float* __restrict__ mem_rec,
         int N, int K)
{
    __shared__ float As[BK][BM + PAD];
    __shared__ float Bs[BK][BN + PAD];

    const float* __restrict__ h = hIn ? hIn : sel_spk(layer - 1);

    const int bm = blockIdx.y * BM;
    const int bn = blockIdx.x * BN;
    const int tid = threadIdx.x;
    const int lk = tid & 15;   // k index for loads (coalesced)
    const int lr = tid >> 4;   // row index for loads
    const int tx = tid & 15;   // 4-col group for compute
    const int ty = tid >> 4;   // 4-row group for compute

    float acc[4][4];
#pragma unroll
    for (int i = 0; i < 4; i++)
#pragma unroll
        for (int j = 0; j < 4; j++) acc[i][j] = 0.f;

    for (int k0 = 0; k0 < K; k0 += BK) {
        const int kg = k0 + lk;
        const bool kv = (kg < K);
#pragma unroll
        for (int i = 0; i < 4; i++) {
            int m = bm + lr + 16 * i;      // M=2048 divisible by 64, always valid
            As[lk][lr + 16 * i] = kv ? h[(long)m * K + kg] : 0.f;
            int n = bn + lr + 16 * i;
            Bs[lk][lr + 16 * i] = (kv && n < N) ? W[(long)n * K + kg] : 0.f;
        }
        __syncthreads();
#pragma unroll
        for (int kk = 0; kk < BK; kk++) {
            float4 av = *(const float4*)&As[kk][ty * 4];
            float4 bv = *(const float4*)&Bs[kk][tx * 4];
            float a[4]  = {av.x, av.y, av.z, av.w};
            float b4[4] = {bv.x, bv.y, bv.z, bv.w};
#pragma unroll
            for (int i = 0; i < 4; i++)
#pragma unroll
                for (int j = 0; j < 4; j++) acc[i][j] = fmaf(a[i], b4[j], acc[i][j]);
        }
        __syncthreads();
    }

    float* __restrict__ mem = sel_mem(layer);
    float* __restrict__ spk_out = (MODE == 1) ? sel_spk(layer) : nullptr;

#pragma unroll
    for (int i = 0; i < 4; i++) {
        const int m = bm + ty * 4 + i;
#pragma unroll
        for (int j = 0; j < 4; j++) {
            const int n = bn + tx * 4 + j;
            if (n < N) {
                float cur = fmaxf(acc[i][j] + bias[n], 0.f);
                long idx = (long)m * N + n;
                if (MODE == 0) {
                    g_cur1[idx] = cur;
                } else {
                    float mm  = mem[idx];
                    float rst = (mm > 1.f) ? 1.f : 0.f;
                    float mn  = 0.95f * mm + cur - rst;
                    mem[idx]  = mn;
                    float s   = (mn > 1.f) ? 1.f : 0.f;
                    if (MODE == 1) {
                        spk_out[idx] = s;
                    } else {
                        spk_rec[idx] = s;
                        mem_rec[idx] = tanhf(mn);
                    }
                }
            }
        }
    }
}

// ---------------- launch -----------------------------------------------
extern "C" void kernel_launch(void* const* d_in, const int* in_sizes, int n_in,
                              void* d_out, int out_size)
{
    const float* x = (const float*)d_in[0];
    const float* W[5];
    const float* b[5];
    for (int i = 0; i < 5; i++) {
        W[i] = (const float*)d_in[1 + 2 * i];
        b[i] = (const float*)d_in[2 + 2 * i];
    }
    float* spk_rec = (float*)d_out;
    float* mem_rec = spk_rec + (long)NSTEPS * Bsz * D5;

    // reset membrane state (deterministic across graph replays)
    zero_mems<<<592, 256>>>();

    // layer-1 current is constant across all 25 steps: compute once
    {
        dim3 g((D1 + BN - 1) / BN, Bsz / BM);
        gemm_lif<0><<<g, 256>>>(x, W[0], b[0], 1, nullptr, nullptr, D1, D0);
    }

    const int Ns[5] = {D1, D2, D3, D4, D5};
    const int Ks[5] = {D0, D1, D2, D3, D4};

    for (int t = 0; t < NSTEPS; t++) {
        lif1_step<<<(Bsz * D1 + 255) / 256, 256>>>();
        for (int L = 2; L <= 4; L++) {
            dim3 g((Ns[L - 1] + BN - 1) / BN, Bsz / BM);
            gemm_lif<1><<<g, 256>>>(nullptr, W[L - 1], b[L - 1], L,
                                    nullptr, nullptr, Ns[L - 1], Ks[L - 1]);
        }
        dim3 g5((D5 + BN - 1) / BN, Bsz / BM);
        gemm_lif<2><<<g5, 256>>>(nullptr, W[4], b[4], 5,
                                 spk_rec + (long)t * Bsz * D5,
                                 mem_rec + (long)t * Bsz * D5,
                                 D5, D4);
    }
}

// round 8
// speedup vs baseline: 1.5201x; 1.5201x over previous
#include <cuda_runtime.h>
#include <cuda_bf16.h>
#include <math.h>
#include <stdint.h>

// ---------------- problem constants ----------------
constexpr int Bsz    = 2048;
constexpr int NSTEPS = 25;
constexpr int D0 = 100;
constexpr int D1 = 128, D2 = 256, D3 = 512, D4 = 1024, D5 = 784;
constexpr int D5P = 896;   // 784 padded to multiple of 128

// ---------------- persistent device state ----------------
__device__ float g_cur1[Bsz * D1];
__device__ float g_mem1[Bsz * D1];
__device__ float g_mem2[Bsz * D2];
__device__ float g_mem3[Bsz * D3];
__device__ float g_mem4[Bsz * D4];
__device__ float g_mem5[Bsz * D5];
__device__ __nv_bfloat16 g_spkb1[Bsz * D1];
__device__ __nv_bfloat16 g_spkb2[Bsz * D2];
__device__ __nv_bfloat16 g_spkb3[Bsz * D3];
__device__ __nv_bfloat16 g_spkb4[Bsz * D4];
// 3-way bf16 weight splits (hi, mid, lo concatenated), neuron dim padded
__device__ __nv_bfloat16 g_ws2[3 * D2  * D1];
__device__ __nv_bfloat16 g_ws3[3 * D3  * D2];
__device__ __nv_bfloat16 g_ws4[3 * D4  * D3];
__device__ __nv_bfloat16 g_ws5[3 * D5P * D4];

// ---------------- per-layer global selection ----------
template <int L> __device__ __forceinline__ const __nv_bfloat16* wsplit_ptr() {
    if constexpr (L == 2) return g_ws2;
    else if constexpr (L == 3) return g_ws3;
    else if constexpr (L == 4) return g_ws4;
    else return g_ws5;
}
template <int L> __device__ __forceinline__ __nv_bfloat16* wsplit_ptr_mut() {
    if constexpr (L == 2) return g_ws2;
    else if constexpr (L == 3) return g_ws3;
    else if constexpr (L == 4) return g_ws4;
    else return g_ws5;
}
template <int L> __device__ __forceinline__ const __nv_bfloat16* spkin_ptr() {
    if constexpr (L == 2) return g_spkb1;
    else if constexpr (L == 3) return g_spkb2;
    else if constexpr (L == 4) return g_spkb3;
    else return g_spkb4;
}
template <int L> __device__ __forceinline__ __nv_bfloat16* spkout_ptr() {
    if constexpr (L == 2) return g_spkb2;
    else if constexpr (L == 3) return g_spkb3;
    else return g_spkb4;
}
template <int L> __device__ __forceinline__ float* mem_ptr() {
    if constexpr (L == 2) return g_mem2;
    else if constexpr (L == 3) return g_mem3;
    else if constexpr (L == 4) return g_mem4;
    else return g_mem5;
}

// ---------------- asm helpers (portable sm_80-class ISA) ----------
__device__ __forceinline__ void cpasync16(void* dst, const void* src) {
    uint32_t d = (uint32_t)__cvta_generic_to_shared(dst);
    asm volatile("cp.async.cg.shared.global [%0], [%1], 16;" :: "r"(d), "l"(src) : "memory");
}
__device__ __forceinline__ void cp_commit() { asm volatile("cp.async.commit_group;" ::: "memory"); }
template <int N> __device__ __forceinline__ void cp_wait() {
    asm volatile("cp.async.wait_group %0;" :: "n"(N) : "memory");
}
__device__ __forceinline__ void ldsm4(uint32_t* r, const void* p) {
    uint32_t a = (uint32_t)__cvta_generic_to_shared(p);
    asm volatile("ldmatrix.sync.aligned.m8n8.x4.shared.b16 {%0,%1,%2,%3}, [%4];"
                 : "=r"(r[0]), "=r"(r[1]), "=r"(r[2]), "=r"(r[3]) : "r"(a));
}
// mma with C=0 and EARLYCLOBBER outputs (never alias inputs), then software
// IEEE fp32 accumulation in CUDA cores (avoids long HW accumulator chains).
__device__ __forceinline__ void mma16816_acc(float* c, const uint32_t* a, uint32_t b0, uint32_t b1) {
    float d0, d1, d2, d3;
    asm volatile("mma.sync.aligned.m16n8k16.row.col.f32.bf16.bf16.f32 "
                 "{%0,%1,%2,%3}, {%4,%5,%6,%7}, {%8,%9}, {%10,%10,%10,%10};"
                 : "=&f"(d0), "=&f"(d1), "=&f"(d2), "=&f"(d3)
                 : "r"(a[0]), "r"(a[1]), "r"(a[2]), "r"(a[3]), "r"(b0), "r"(b1), "f"(0.f));
    c[0] += d0; c[1] += d1; c[2] += d2; c[3] += d3;
}

// ---------------- small kernels ----------------
__global__ void zero_mems() {
    long i = (long)blockIdx.x * blockDim.x + threadIdx.x;
    long stride = (long)gridDim.x * blockDim.x;
    for (long j = i; j < (long)Bsz * D1; j += stride) g_mem1[j] = 0.f;
    for (long j = i; j < (long)Bsz * D2; j += stride) g_mem2[j] = 0.f;
    for (long j = i; j < (long)Bsz * D3; j += stride) g_mem3[j] = 0.f;
    for (long j = i; j < (long)Bsz * D4; j += stride) g_mem4[j] = 0.f;
    for (long j = i; j < (long)Bsz * D5; j += stride) g_mem5[j] = 0.f;
}

template <int L, int N, int K, int NPAD>
__global__ void split_w(const float* __restrict__ W) {
    __nv_bfloat16* out = wsplit_ptr_mut<L>();
    int i = blockIdx.x * blockDim.x + threadIdx.x;
    constexpr int tot = NPAD * K;
    if (i < tot) {
        int n = i / K;
        float w = (n < N) ? W[i] : 0.f;
        __nv_bfloat16 hi = __float2bfloat16(w);
        float r = w - __bfloat162float(hi);
        __nv_bfloat16 mid = __float2bfloat16(r);
        float r2 = r - __bfloat162float(mid);
        out[i]           = hi;
        out[tot + i]     = mid;
        out[2 * tot + i] = __float2bfloat16(r2);
    }
}

__global__ void lif1_step() {
    int i = blockIdx.x * blockDim.x + threadIdx.x;
    if (i < Bsz * D1) {
        float cur = g_cur1[i];
        float mm  = g_mem1[i];
        float rst = (mm > 1.f) ? 1.f : 0.f;
        float mn  = 0.95f * mm + cur - rst;
        g_mem1[i] = mn;
        g_spkb1[i] = __float2bfloat16((mn > 1.f) ? 1.f : 0.f);
    }
}

// layer-1 fp32 GEMM (K=100, non-binary input): g_cur1 = relu(x@W1^T + b1), once
__global__ void __launch_bounds__(256)
gemm1(const float* __restrict__ x, const float* __restrict__ W, const float* __restrict__ bias)
{
    constexpr int N = D1, K = D0;
    __shared__ float As[16][68];
    __shared__ float Bs[16][68];
    const int bm = blockIdx.y * 64, bn = blockIdx.x * 64;
    const int tid = threadIdx.x;
    const int lk = tid & 15, lr = tid >> 4;
    const int tx = tid & 15, ty = tid >> 4;
    float acc[4][4] = {};
    for (int k0 = 0; k0 < K; k0 += 16) {
        const int kg = k0 + lk;
        const bool kv = (kg < K);
#pragma unroll
        for (int i = 0; i < 4; i++) {
            As[lk][lr + 16 * i] = kv ? x[(long)(bm + lr + 16 * i) * K + kg] : 0.f;
            Bs[lk][lr + 16 * i] = kv ? W[(long)(bn + lr + 16 * i) * K + kg] : 0.f;
        }
        __syncthreads();
#pragma unroll
        for (int kk = 0; kk < 16; kk++) {
            float4 av = *(const float4*)&As[kk][ty * 4];
            float4 bv = *(const float4*)&Bs[kk][tx * 4];
            float a[4] = {av.x, av.y, av.z, av.w};
            float b4[4] = {bv.x, bv.y, bv.z, bv.w};
#pragma unroll
            for (int i = 0; i < 4; i++)
#pragma unroll
                for (int j = 0; j < 4; j++) acc[i][j] = fmaf(a[i], b4[j], acc[i][j]);
        }
        __syncthreads();
    }
#pragma unroll
    for (int i = 0; i < 4; i++)
#pragma unroll
        for (int j = 0; j < 4; j++) {
            int m = bm + ty * 4 + i, n = bn + tx * 4 + j;
            g_cur1[(long)m * N + n] = fmaxf(acc[i][j] + bias[n], 0.f);
        }
}

// ---------------- bf16 mma.sync fused GEMM + LIF ---------------------------
// CTA: 128 batch x 128 neuron, BK=32, 8 warps (2x4), warp tile 64x32.
// 3 weight splits; mma C=0 + software fp32 accumulation (IEEE adds).
template <int L, int MODE, int N, int K, int NPAD>
__global__ void __launch_bounds__(256, 1)
snn_mma(const float* __restrict__ bias, float* __restrict__ spk_rec, float* __restrict__ mem_rec)
{
    constexpr int BK = 32;
    constexpr int CH = K / BK;
    constexpr int CTOT = 3 * CH;       // chunks across the 3 weight splits
    constexpr int LDS = BK + 8;        // padded row (80B, 16B-aligned rows)

    __shared__ __nv_bfloat16 As[2][128][LDS];
    __shared__ __nv_bfloat16 Bs[2][128][LDS];

    const __nv_bfloat16* __restrict__ spk = spkin_ptr<L>();
    const __nv_bfloat16* __restrict__ wsp = wsplit_ptr<L>();
    float* __restrict__ mem = mem_ptr<L>();

    const int b0 = blockIdx.y * 128;   // batch tile
    const int n0 = blockIdx.x * 128;   // neuron tile (padded space)
    const int tid = threadIdx.x;
    const int lane = tid & 31, wid = tid >> 5;
    const int wm = wid & 1, wn = wid >> 1;

    const int lrow = tid >> 2;
    const int lseg = (tid & 3) * 8;

    float acc[4][4][4] = {};

    auto load_chunk = [&](int c, int buf) {
        const int s  = c / CH;
        const int k0 = (c % CH) * BK;
        const __nv_bfloat16* wb = wsp + (size_t)s * NPAD * K;
#pragma unroll
        for (int h = 0; h < 2; h++) {
            const int r = lrow + h * 64;
            cpasync16(&As[buf][r][lseg], spk + (size_t)(b0 + r) * K + k0 + lseg);
            cpasync16(&Bs[buf][r][lseg], wb  + (size_t)(n0 + r) * K + k0 + lseg);
        }
        cp_commit();
    };

    load_chunk(0, 0);
    for (int c = 0; c < CTOT; c++) {
        const int buf = c & 1;
        if (c + 1 < CTOT) { load_chunk(c + 1, buf ^ 1); cp_wait<1>(); }
        else              { cp_wait<0>(); }
        __syncthreads();
#pragma unroll
        for (int kk = 0; kk < BK; kk += 16) {
            uint32_t a[4][4];
#pragma unroll
            for (int i = 0; i < 4; i++)
                ldsm4(a[i], &As[buf][wm * 64 + i * 16 + (lane & 15)][kk + (lane >> 4) * 8]);
            uint32_t b[2][4];
#pragma unroll
            for (int jj = 0; jj < 2; jj++)
                ldsm4(b[jj], &Bs[buf][wn * 32 + jj * 16 + (lane & 7) + (lane >> 4) * 8]
                                      [kk + ((lane >> 3) & 1) * 8]);
#pragma unroll
            for (int i = 0; i < 4; i++)
#pragma unroll
                for (int j = 0; j < 4; j++)
                    mma16816_acc(acc[i][j], a[i], b[j >> 1][(j & 1) * 2], b[j >> 1][(j & 1) * 2 + 1]);
        }
        __syncthreads();
    }

    // ---------------- fused LIF epilogue ----------------
    const int mrow = lane >> 2;
    const int ncol = 2 * (lane & 3);
#pragma unroll
    for (int i = 0; i < 4; i++) {
        const int gm0 = b0 + wm * 64 + i * 16 + mrow;
#pragma unroll
        for (int j = 0; j < 4; j++) {
            const int gn = n0 + wn * 32 + j * 8 + ncol;
            if (gn < N) {
                const float bv0 = bias[gn], bv1 = bias[gn + 1];
#pragma unroll
                for (int h = 0; h < 2; h++) {
                    const int gm = gm0 + h * 8;
                    const size_t idx = (size_t)gm * N + gn;
                    float2 mm = *(const float2*)(mem + idx);
                    const float v0 = acc[i][j][h * 2], v1 = acc[i][j][h * 2 + 1];
                    const float cur0 = fmaxf(v0 + bv0, 0.f);
                    const float cur1 = fmaxf(v1 + bv1, 0.f);
                    const float mn0 = 0.95f * mm.x + cur0 - ((mm.x > 1.f) ? 1.f : 0.f);
                    const float mn1 = 0.95f * mm.y + cur1 - ((mm.y > 1.f) ? 1.f : 0.f);
                    *(float2*)(mem + idx) = make_float2(mn0, mn1);
                    const float s0 = (mn0 > 1.f) ? 1.f : 0.f;
                    const float s1 = (mn1 > 1.f) ? 1.f : 0.f;
                    if (MODE == 1) {
                        __nv_bfloat162 sp;
                        sp.x = __float2bfloat16(s0);
                        sp.y = __float2bfloat16(s1);
                        *(__nv_bfloat162*)(spkout_ptr<L>() + idx) = sp;
                    } else {
                        *(float2*)(spk_rec + idx) = make_float2(s0, s1);
                        *(float2*)(mem_rec + idx) = make_float2(tanhf(mn0), tanhf(mn1));
                    }
                }
            }
        }
    }
}

// ---------------- launch -----------------------------------------------
extern "C" void kernel_launch(void* const* d_in, const int* in_sizes, int n_in,
                              void* d_out, int out_size)
{
    const float* x = (const float*)d_in[0];
    const float* W[5];
    const float* b[5];
    for (int i = 0; i < 5; i++) {
        W[i] = (const float*)d_in[1 + 2 * i];
        b[i] = (const float*)d_in[2 + 2 * i];
    }
    float* spk_rec = (float*)d_out;
    float* mem_rec = spk_rec + (long)NSTEPS * Bsz * D5;

    zero_mems<<<592, 256>>>();
    split_w<2, D2, D1, D2 ><<<(D2  * D1 + 255) / 256, 256>>>(W[1]);
    split_w<3, D3, D2, D3 ><<<(D3  * D2 + 255) / 256, 256>>>(W[2]);
    split_w<4, D4, D3, D4 ><<<(D4  * D3 + 255) / 256, 256>>>(W[3]);
    split_w<5, D5, D4, D5P><<<(D5P * D4 + 255) / 256, 256>>>(W[4]);
    gemm1<<<dim3(D1 / 64, Bsz / 64), 256>>>(x, W[0], b[0]);

    for (int t = 0; t < NSTEPS; t++) {
        lif1_step<<<(Bsz * D1 + 255) / 256, 256>>>();
        snn_mma<2, 1, D2, D1, D2 ><<<dim3(D2  / 128, Bsz / 128), 256>>>(b[1], nullptr, nullptr);
        snn_mma<3, 1, D3, D2, D3 ><<<dim3(D3  / 128, Bsz / 128), 256>>>(b[2], nullptr, nullptr);
        snn_mma<4, 1, D4, D3, D4 ><<<dim3(D4  / 128, Bsz / 128), 256>>>(b[3], nullptr, nullptr);
        snn_mma<5, 2, D5, D4, D5P><<<dim3(D5P / 128, Bsz / 128), 256>>>(
            b[4], spk_rec + (long)t * Bsz * D5, mem_rec + (long)t * Bsz * D5);
    }
}

// round 14
// speedup vs baseline: 1.9861x; 1.3066x over previous
#include <cuda_runtime.h>
#include <cuda_bf16.h>
#include <math.h>
#include <stdint.h>

// ---------------- problem constants ----------------
constexpr int Bsz    = 2048;
constexpr int NSTEPS = 25;
constexpr int D0 = 100;
constexpr int D1 = 128, D2 = 256, D3 = 512, D4 = 1024, D5 = 784;
constexpr int D5P = 896;   // 784 padded to multiple of 128

// ---------------- persistent device state ----------------
__device__ float g_cur1[Bsz * D1];
__device__ float g_mem1[Bsz * D1];
__device__ float g_mem2[Bsz * D2];
__device__ float g_mem3[Bsz * D3];
__device__ float g_mem4[Bsz * D4];
__device__ float g_mem5[Bsz * D5];
__device__ __nv_bfloat16 g_spkb1[Bsz * D1];
__device__ __nv_bfloat16 g_spkb2[Bsz * D2];
__device__ __nv_bfloat16 g_spkb3[Bsz * D3];
__device__ __nv_bfloat16 g_spkb4[Bsz * D4];
// 3-way bf16 weight splits (hi, mid, lo concatenated), neuron dim padded
__device__ __nv_bfloat16 g_ws2[3 * D2  * D1];
__device__ __nv_bfloat16 g_ws3[3 * D3  * D2];
__device__ __nv_bfloat16 g_ws4[3 * D4  * D3];
__device__ __nv_bfloat16 g_ws5[3 * D5P * D4];

// ---------------- per-layer global selection ----------
template <int L> __device__ __forceinline__ const __nv_bfloat16* wsplit_ptr() {
    if constexpr (L == 2) return g_ws2;
    else if constexpr (L == 3) return g_ws3;
    else if constexpr (L == 4) return g_ws4;
    else return g_ws5;
}
template <int L> __device__ __forceinline__ __nv_bfloat16* wsplit_ptr_mut() {
    if constexpr (L == 2) return g_ws2;
    else if constexpr (L == 3) return g_ws3;
    else if constexpr (L == 4) return g_ws4;
    else return g_ws5;
}
template <int L> __device__ __forceinline__ const __nv_bfloat16* spkin_ptr() {
    if constexpr (L == 2) return g_spkb1;
    else if constexpr (L == 3) return g_spkb2;
    else if constexpr (L == 4) return g_spkb3;
    else return g_spkb4;
}
template <int L> __device__ __forceinline__ __nv_bfloat16* spkout_ptr() {
    if constexpr (L == 2) return g_spkb2;
    else if constexpr (L == 3) return g_spkb3;
    else return g_spkb4;
}
template <int L> __device__ __forceinline__ float* mem_ptr() {
    if constexpr (L == 2) return g_mem2;
    else if constexpr (L == 3) return g_mem3;
    else if constexpr (L == 4) return g_mem4;
    else return g_mem5;
}

// ---------------- asm helpers (portable sm_80-class ISA) ----------
__device__ __forceinline__ void cpasync16(void* dst, const void* src) {
    uint32_t d = (uint32_t)__cvta_generic_to_shared(dst);
    asm volatile("cp.async.cg.shared.global [%0], [%1], 16;" :: "r"(d), "l"(src) : "memory");
}
__device__ __forceinline__ void cp_commit() { asm volatile("cp.async.commit_group;" ::: "memory"); }
template <int N> __device__ __forceinline__ void cp_wait() {
    asm volatile("cp.async.wait_group %0;" :: "n"(N) : "memory");
}
__device__ __forceinline__ void ldsm4(uint32_t* r, const void* p) {
    uint32_t a = (uint32_t)__cvta_generic_to_shared(p);
    asm volatile("ldmatrix.sync.aligned.m8n8.x4.shared.b16 {%0,%1,%2,%3}, [%4];"
                 : "=r"(r[0]), "=r"(r[1]), "=r"(r[2]), "=r"(r[3]) : "r"(a));
}
// mma with C=0 and EARLYCLOBBER outputs (never alias inputs), then software
// IEEE fp32 accumulation in CUDA cores (avoids long HW accumulator chains).
__device__ __forceinline__ void mma16816_acc(float* c, const uint32_t* a, uint32_t b0, uint32_t b1) {
    float d0, d1, d2, d3;
    asm volatile("mma.sync.aligned.m16n8k16.row.col.f32.bf16.bf16.f32 "
                 "{%0,%1,%2,%3}, {%4,%5,%6,%7}, {%8,%9}, {%10,%10,%10,%10};"
                 : "=&f"(d0), "=&f"(d1), "=&f"(d2), "=&f"(d3)
                 : "r"(a[0]), "r"(a[1]), "r"(a[2]), "r"(a[3]), "r"(b0), "r"(b1), "f"(0.f));
    c[0] += d0; c[1] += d1; c[2] += d2; c[3] += d3;
}

// ---------------- LIF-for-layer-1 helper (used by two kernels) ----------
__device__ __forceinline__ void lif1_update(int i) {
    float cur = g_cur1[i];
    float mm  = g_mem1[i];
    float rst = (mm > 1.f) ? 1.f : 0.f;
    float mn  = 0.95f * mm + cur - rst;
    g_mem1[i] = mn;
    g_spkb1[i] = __float2bfloat16((mn > 1.f) ? 1.f : 0.f);
}

// ---------------- small kernels ----------------
__global__ void zero_mems() {
    long i = (long)blockIdx.x * blockDim.x + threadIdx.x;
    long stride = (long)gridDim.x * blockDim.x;
    for (long j = i; j < (long)Bsz * D1; j += stride) g_mem1[j] = 0.f;
    for (long j = i; j < (long)Bsz * D2; j += stride) g_mem2[j] = 0.f;
    for (long j = i; j < (long)Bsz * D3; j += stride) g_mem3[j] = 0.f;
    for (long j = i; j < (long)Bsz * D4; j += stride) g_mem4[j] = 0.f;
    for (long j = i; j < (long)Bsz * D5; j += stride) g_mem5[j] = 0.f;
}

template <int L, int N, int K, int NPAD>
__global__ void split_w(const float* __restrict__ W) {
    __nv_bfloat16* out = wsplit_ptr_mut<L>();
    int i = blockIdx.x * blockDim.x + threadIdx.x;
    constexpr int tot = NPAD * K;
    if (i < tot) {
        int n = i / K;
        float w = (n < N) ? W[i] : 0.f;
        __nv_bfloat16 hi = __float2bfloat16(w);
        float r = w - __bfloat162float(hi);
        __nv_bfloat16 mid = __float2bfloat16(r);
        float r2 = r - __bfloat162float(mid);
        out[i]           = hi;
        out[tot + i]     = mid;
        out[2 * tot + i] = __float2bfloat16(r2);
    }
}

__global__ void lif1_step() {
    int i = blockIdx.x * blockDim.x + threadIdx.x;
    if (i < Bsz * D1) lif1_update(i);
}

// layer-1 fp32 GEMM (K=100, non-binary input): g_cur1 = relu(x@W1^T + b1), once
__global__ void __launch_bounds__(256)
gemm1(const float* __restrict__ x, const float* __restrict__ W, const float* __restrict__ bias)
{
    constexpr int N = D1, K = D0;
    __shared__ float As[16][68];
    __shared__ float Bs[16][68];
    const int bm = blockIdx.y * 64, bn = blockIdx.x * 64;
    const int tid = threadIdx.x;
    const int lk = tid & 15, lr = tid >> 4;
    const int tx = tid & 15, ty = tid >> 4;
    float acc[4][4] = {};
    for (int k0 = 0; k0 < K; k0 += 16) {
        const int kg = k0 + lk;
        const bool kv = (kg < K);
#pragma unroll
        for (int i = 0; i < 4; i++) {
            As[lk][lr + 16 * i] = kv ? x[(long)(bm + lr + 16 * i) * K + kg] : 0.f;
            Bs[lk][lr + 16 * i] = kv ? W[(long)(bn + lr + 16 * i) * K + kg] : 0.f;
        }
        __syncthreads();
#pragma unroll
        for (int kk = 0; kk < 16; kk++) {
            float4 av = *(const float4*)&As[kk][ty * 4];
            float4 bv = *(const float4*)&Bs[kk][tx * 4];
            float a[4] = {av.x, av.y, av.z, av.w};
            float b4[4] = {bv.x, bv.y, bv.z, bv.w};
#pragma unroll
            for (int i = 0; i < 4; i++)
#pragma unroll
                for (int j = 0; j < 4; j++) acc[i][j] = fmaf(a[i], b4[j], acc[i][j]);
        }
        __syncthreads();
    }
#pragma unroll
    for (int i = 0; i < 4; i++)
#pragma unroll
        for (int j = 0; j < 4; j++) {
            int m = bm + ty * 4 + i, n = bn + tx * 4 + j;
            g_cur1[(long)m * N + n] = fmaxf(acc[i][j] + bias[n], 0.f);
        }
}

// ---------------- bf16 mma.sync fused GEMM + LIF ---------------------------
// CTA: BM batch x 128 neuron, BK=32, 8 warps (2x4), warp tile (BM/2)x32.
// k-major chunks: per chunk, ONE spike tile + 3 weight-split tiles resident;
// A-fragments ldsm'd once per k16 and reused across the 3 splits.
// 3 weight splits; mma C=0 + software fp32 accumulation (IEEE adds) -- R8 numerics.
template <int L, int MODE, int N, int K, int NPAD, int BM>
__global__ void __launch_bounds__(256, 1)
snn_mma(const float* __restrict__ bias, float* __restrict__ spk_rec, float* __restrict__ mem_rec)
{
    constexpr int BK  = 32;
    constexpr int CH  = K / BK;        // k-chunks
    constexpr int LDS = BK + 8;        // padded row (80B, 16B-aligned rows)
    constexpr int MI  = BM / 32;       // a-fragments per warp (m16 each)
    constexpr int AROWS = BM;
    constexpr int STAGE = (AROWS + 3 * 128) * LDS;   // elements per stage

    extern __shared__ __nv_bfloat16 smem[];
    auto As = [&](int st) { return smem + st * STAGE; };
    auto Bs = [&](int st, int s) { return smem + st * STAGE + AROWS * LDS + s * 128 * LDS; };

    const __nv_bfloat16* __restrict__ spk = spkin_ptr<L>();
    const __nv_bfloat16* __restrict__ wsp = wsplit_ptr<L>();
    float* __restrict__ mem = mem_ptr<L>();

    const int b0 = blockIdx.y * BM;    // batch tile
    const int n0 = blockIdx.x * 128;   // neuron tile (padded space)
    const int tid = threadIdx.x;
    const int lane = tid & 31, wid = tid >> 5;
    const int wm = wid & 1, wn = wid >> 1;

    const int lrow = tid >> 2;         // 0..63
    const int lseg = (tid & 3) * 8;    // 16B granule within a 64B row

    float acc[MI][4][4] = {};

    auto load_chunk = [&](int kc, int buf) {
        const int k0 = kc * BK;
#pragma unroll
        for (int h = 0; h < BM / 64; h++) {
            const int r = lrow + h * 64;
            cpasync16(As(buf) + r * LDS + lseg, spk + (size_t)(b0 + r) * K + k0 + lseg);
        }
#pragma unroll
        for (int s = 0; s < 3; s++) {
            const __nv_bfloat16* wb = wsp + (size_t)s * NPAD * K;
#pragma unroll
            for (int h = 0; h < 2; h++) {
                const int r = lrow + h * 64;
                cpasync16(Bs(buf, s) + r * LDS + lseg, wb + (size_t)(n0 + r) * K + k0 + lseg);
            }
        }
        cp_commit();
    };

    load_chunk(0, 0);
    for (int c = 0; c < CH; c++) {
        const int buf = c & 1;
        if (c + 1 < CH) { load_chunk(c + 1, buf ^ 1); cp_wait<1>(); }
        else            { cp_wait<0>(); }
        __syncthreads();
#pragma unroll
        for (int kk = 0; kk < BK; kk += 16) {
            uint32_t a[MI][4];
#pragma unroll
            for (int i = 0; i < MI; i++)
                ldsm4(a[i], As(buf) + (wm * (BM / 2) + i * 16 + (lane & 15)) * LDS
                                     + kk + (lane >> 4) * 8);
#pragma unroll
            for (int s = 0; s < 3; s++) {
                uint32_t b[2][4];
#pragma unroll
                for (int jj = 0; jj < 2; jj++)
                    ldsm4(b[jj], Bs(buf, s) + (wn * 32 + jj * 16 + (lane & 7) + (lane >> 4) * 8) * LDS
                                             + kk + ((lane >> 3) & 1) * 8);
#pragma unroll
                for (int i = 0; i < MI; i++)
#pragma unroll
                    for (int j = 0; j < 4; j++)
                        mma16816_acc(acc[i][j], a[i], b[j >> 1][(j & 1) * 2], b[j >> 1][(j & 1) * 2 + 1]);
            }
        }
        __syncthreads();
    }

    // ---------------- fused LIF epilogue ----------------
    const int mrow = lane >> 2;
    const int ncol = 2 * (lane & 3);
#pragma unroll
    for (int i = 0; i < MI; i++) {
        const int gm0 = b0 + wm * (BM / 2) + i * 16 + mrow;
#pragma unroll
        for (int j = 0; j < 4; j++) {
            const int gn = n0 + wn * 32 + j * 8 + ncol;
            if (gn < N) {
                const float bv0 = bias[gn], bv1 = bias[gn + 1];
#pragma unroll
                for (int h = 0; h < 2; h++) {
                    const int gm = gm0 + h * 8;
                    const size_t idx = (size_t)gm * N + gn;
                    float2 mm = *(const float2*)(mem + idx);
                    const float v0 = acc[i][j][h * 2], v1 = acc[i][j][h * 2 + 1];
                    const float cur0 = fmaxf(v0 + bv0, 0.f);
                    const float cur1 = fmaxf(v1 + bv1, 0.f);
                    const float mn0 = 0.95f * mm.x + cur0 - ((mm.x > 1.f) ? 1.f : 0.f);
                    const float mn1 = 0.95f * mm.y + cur1 - ((mm.y > 1.f) ? 1.f : 0.f);
                    *(float2*)(mem + idx) = make_float2(mn0, mn1);
                    const float s0 = (mn0 > 1.f) ? 1.f : 0.f;
                    const float s1 = (mn1 > 1.f) ? 1.f : 0.f;
                    if (MODE == 1) {
                        __nv_bfloat162 sp;
                        sp.x = __float2bfloat16(s0);
                        sp.y = __float2bfloat16(s1);
                        *(__nv_bfloat162*)(spkout_ptr<L>() + idx) = sp;
                    } else {
                        *(float2*)(spk_rec + idx) = make_float2(s0, s1);
                        *(float2*)(mem_rec + idx) = make_float2(tanhf(mn0), tanhf(mn1));
                    }
                }
            }
        }
    }

    // ---------------- fold next step's layer-1 LIF into the L5 kernel ------
    if (MODE == 2) {
        const int cta = blockIdx.y * gridDim.x + blockIdx.x;
        const int nthr = gridDim.x * gridDim.y * 256;
        for (int i = cta * 256 + tid; i < Bsz * D1; i += nthr) lif1_update(i);
    }
}

// ---------------- launch -----------------------------------------------
extern "C" void kernel_launch(void* const* d_in, const int* in_sizes, int n_in,
                              void* d_out, int out_size)
{
    const float* x = (const float*)d_in[0];
    const float* W[5];
    const float* b[5];
    for (int i = 0; i < 5; i++) {
        W[i] = (const float*)d_in[1 + 2 * i];
        b[i] = (const float*)d_in[2 + 2 * i];
    }
    float* spk_rec = (float*)d_out;
    float* mem_rec = spk_rec + (long)NSTEPS * Bsz * D5;

    constexpr int LDS = 40;
    constexpr int SM64  = 2 * (64  + 384) * LDS * 2;   // 71680 B
    constexpr int SM128 = 2 * (128 + 384) * LDS * 2;   // 81920 B

    static bool attr_done = false;
    if (!attr_done) {
        cudaFuncSetAttribute(snn_mma<2, 1, D2, D1, D2,  64>,
                             cudaFuncAttributeMaxDynamicSharedMemorySize, SM64);
        cudaFuncSetAttribute(snn_mma<3, 1, D3, D2, D3,  64>,
                             cudaFuncAttributeMaxDynamicSharedMemorySize, SM64);
        cudaFuncSetAttribute(snn_mma<4, 1, D4, D3, D4, 128>,
                             cudaFuncAttributeMaxDynamicSharedMemorySize, SM128);
        cudaFuncSetAttribute(snn_mma<5, 2, D5, D4, D5P, 128>,
                             cudaFuncAttributeMaxDynamicSharedMemorySize, SM128);
        attr_done = true;
    }

    zero_mems<<<592, 256>>>();
    split_w<2, D2, D1, D2 ><<<(D2  * D1 + 255) / 256, 256>>>(W[1]);
    split_w<3, D3, D2, D3 ><<<(D3  * D2 + 255) / 256, 256>>>(W[2]);
    split_w<4, D4, D3, D4 ><<<(D4  * D3 + 255) / 256, 256>>>(W[3]);
    split_w<5, D5, D4, D5P><<<(D5P * D4 + 255) / 256, 256>>>(W[4]);
    gemm1<<<dim3(D1 / 64, Bsz / 64), 256>>>(x, W[0], b[0]);
    lif1_step<<<(Bsz * D1 + 255) / 256, 256>>>();   // step 0 spikes; steps 1.. in L5 tail

    for (int t = 0; t < NSTEPS; t++) {
        snn_mma<2, 1, D2, D1, D2,  64><<<dim3(D2  / 128, Bsz / 64),  256, SM64 >>>(b[1], nullptr, nullptr);
        snn_mma<3, 1, D3, D2, D3,  64><<<dim3(D3  / 128, Bsz / 64),  256, SM64 >>>(b[2], nullptr, nullptr);
        snn_mma<4, 1, D4, D3, D4, 128><<<dim3(D4  / 128, Bsz / 128), 256, SM128>>>(b[3], nullptr, nullptr);
        snn_mma<5, 2, D5, D4, D5P,128><<<dim3(D5P / 128, Bsz / 128), 256, SM128>>>(
            b[4], spk_rec + (long)t * Bsz * D5, mem_rec + (long)t * Bsz * D5);
    }
}